// round 14
// baseline (speedup 1.0000x reference)
#include <cuda_runtime.h>
#include <cuda_fp16.h>
#include <stdint.h>
#include <string.h>

#define N_PTS 2048
#define M_PTS 512
#define HID   128
#define TJW   32                  // j's per warp-chunk
#define JTW   16                  // warp-chunks per i
#define NCHUNK (N_PTS * JTW)      // 32768
#define NCTA  296                 // 2 per SM
#define NWARPS (NCTA * 8)
#define PI_F  3.14159265358979323846f

// smem pitch for W2: 136 fp16 per row = 272 B -> ldmatrix conflict-free
#define PITCH_B 272

// ---- shared memory layout (bytes) ----
#define SM_W2    0                // [128][136] fp16 (W2^T) 34816
#define SM_B2W3  34816            // 128 x float2 (b2, W3) 1024
#define SM_QX    35840            // 512 x float2 = 4096
#define SM_CF4   39936            // 128 x float4 {W1r0, W1r1, b1, W1r2} 2048
#define SM_WD    41984            // 128 x float (W1r3) 512
#define SM_FLAG  42496            // is_last flag
#define SMEM_TOTAL 42560

// ---- device scratch ----
__device__ __align__(16) float g_part[NCHUNK];
__device__ unsigned int g_done;                    // zero-init; reset each run

// ---------------------------------------------------------------------------
__device__ __forceinline__ float tanh_a32(float x) {
    float r;
    asm("tanh.approx.f32 %0, %1;" : "=f"(r) : "f"(x));
    return r;
}
__device__ __forceinline__ uint32_t tanh_a16x2(uint32_t x2) {
    uint32_t r;
    asm("tanh.approx.f16x2 %0, %1;" : "=r"(r) : "r"(x2));
    return r;
}
__device__ __forceinline__ uint32_t smem_u32(const void* p) {
    uint32_t a;
    asm("{ .reg .u64 t; cvta.to.shared.u64 t, %1; cvt.u32.u64 %0, t; }"
        : "=r"(a) : "l"(p));
    return a;
}
__device__ __forceinline__ void ldsm4(uint32_t& r0, uint32_t& r1,
                                      uint32_t& r2, uint32_t& r3, uint32_t addr) {
    asm volatile("ldmatrix.sync.aligned.m8n8.x4.shared.b16 {%0,%1,%2,%3}, [%4];"
                 : "=r"(r0), "=r"(r1), "=r"(r2), "=r"(r3) : "r"(addr));
}
__device__ __forceinline__ void mma_f16(float* d, const uint32_t* a,
                                        const uint32_t* b) {
    asm volatile(
        "mma.sync.aligned.m16n8k16.row.col.f32.f16.f16.f32 "
        "{%0,%1,%2,%3}, {%4,%5,%6,%7}, {%8,%9}, {%0,%1,%2,%3};"
        : "+f"(d[0]), "+f"(d[1]), "+f"(d[2]), "+f"(d[3])
        : "r"(a[0]), "r"(a[1]), "r"(a[2]), "r"(a[3]), "r"(b[0]), "r"(b[1]));
}
__device__ __forceinline__ uint32_t h2u(__half2 h) {
    uint32_t u; memcpy(&u, &h, 4); return u;
}

// ---------------------------------------------------------------------------
// Single persistent kernel, warp-autonomous chunks, NO h1 smem round-trip:
// each lane computes the 8 A-fragment values it owns (PTX m16n8k16 layout:
// rows r=lane>>2 (+8), cols 2*(lane&3)+{0,1} and +8+{0,1} per k-step),
// packs to half2, tanh.approx.f16x2 -> a-register directly.
// GEMM: 4 n-blocks of 32; B from static W2 smem via ldmatrix.
// Epilogue: tanh.approx.f32 + W3 dot, warp shfl reduce, y register-resident.
// Tail: last CTA (atomic ticket) computes Y and sums g_part -> out.
// ---------------------------------------------------------------------------
__global__ void __launch_bounds__(256, 2) modnet_mma_kernel(
        const float* __restrict__ inp,
        const float* __restrict__ qx,
        const float* __restrict__ ep,
        const float* __restrict__ W1,
        const float* __restrict__ b1,
        const float* __restrict__ W2,
        const float* __restrict__ b2,
        const float* __restrict__ W3,
        const float* __restrict__ b3,
        float* __restrict__ out) {
    extern __shared__ char smem[];
    const uint32_t sb = smem_u32(smem);
    const int tid = threadIdx.x, lane = tid & 31, wid = tid >> 5;

    // ---- prologue: W2^T (fp16), b2/W3, W1 coef pack, qx into smem ----
    for (int e = tid; e < HID * 64; e += 256) {
        int n = e & 127, cp = e >> 7, c = cp * 2;
        __half2 h = __floats2half2_rn(W2[c * HID + n], W2[(c + 1) * HID + n]);
        *(uint32_t*)(smem + SM_W2 + (uint32_t)(n * PITCH_B + cp * 4)) = h2u(h);
    }
    if (tid < HID) {
        float2 v; v.x = b2[tid]; v.y = W3[tid];
        *(float2*)(smem + SM_B2W3 + tid * 8) = v;
        float4 cf;
        cf.x = W1[tid];            // row 0 (x0 weight)
        cf.y = W1[128 + tid];      // row 1 (x1 weight)
        cf.z = b1[tid];
        cf.w = W1[256 + tid];      // row 2 (qx weight)
        *(float4*)(smem + SM_CF4 + tid * 16) = cf;
        *(float*)(smem + SM_WD + tid * 4) = W1[384 + tid];  // row 3 (qy weight)
    }
    for (int e = tid; e < M_PTS * 2; e += 256)
        ((float*)(smem + SM_QX))[e] = qx[e];
    __syncthreads();

    const float2* bw   = (const float2*)(smem + SM_B2W3);
    const float*  qxs  = (const float*)(smem + SM_QX);
    const float4* cf4s = (const float4*)(smem + SM_CF4);
    const float*  wds  = (const float*)(smem + SM_WD);
    const float epi = ep[0] * PI_F;
    const int r  = lane >> 2;            // fragment row group
    const int cq = 2 * (lane & 3);       // fragment col base within k-step

    const uint32_t bAddr0 = sb + SM_W2
        + (uint32_t)((((lane >> 4) << 3) + (lane & 7)) * PITCH_B
                   + ((lane >> 3) & 1) * 16);

    for (int cid = blockIdx.x * 8 + wid; cid < NCHUNK; cid += NWARPS) {
        const int i  = cid >> 4;
        const int j0 = (cid & 15) * TJW;

        const float2 xi = *(const float2*)(inp + 2 * i);

        // q for this lane's 4 fragment rows: j0 + r, r+8, r+16, r+24
        float2 qreg[4];
        #pragma unroll
        for (int kk = 0; kk < 4; kk++)
            qreg[kk] = *(const float2*)(qxs + 2 * (j0 + r + 8 * kk));

        // y for warp's 32 j's: lane l owns j0+l
        float y_own;
        {
            float2 qo = *(const float2*)(qxs + 2 * (j0 + lane));
            y_own = sinf(epi * qo.x) * sinf(epi * qo.y);
        }

        // ---- A fragments computed directly in registers (m32 x k128) ----
        uint32_t ah[2][8][4];
        #pragma unroll
        for (int ks = 0; ks < 8; ks++) {
            const int c0 = ks * 16 + cq;
            float4 ca = cf4s[c0],     cb = cf4s[c0 + 1];
            float4 cc = cf4s[c0 + 8], cd = cf4s[c0 + 9];
            float2 wd01 = *(const float2*)(wds + c0);
            float2 wd89 = *(const float2*)(wds + c0 + 8);
            // per-col base: b1 + x0*w10 + x1*w11
            float ba = fmaf(xi.y, ca.y, fmaf(xi.x, ca.x, ca.z));
            float bb2 = fmaf(xi.y, cb.y, fmaf(xi.x, cb.x, cb.z));
            float bc = fmaf(xi.y, cc.y, fmaf(xi.x, cc.x, cc.z));
            float bd = fmaf(xi.y, cd.y, fmaf(xi.x, cd.x, cd.z));
            #pragma unroll
            for (int kk = 0; kk < 4; kk++) {        // rows r+8*kk
                const float2 q = qreg[kk];
                float v0 = fmaf(q.y, wd01.x, fmaf(q.x, ca.w, ba));
                float v1 = fmaf(q.y, wd01.y, fmaf(q.x, cb.w, bb2));
                float v8 = fmaf(q.y, wd89.x, fmaf(q.x, cc.w, bc));
                float v9 = fmaf(q.y, wd89.y, fmaf(q.x, cd.w, bd));
                uint32_t lo = tanh_a16x2(h2u(__floats2half2_rn(v0, v1)));
                uint32_t hi = tanh_a16x2(h2u(__floats2half2_rn(v8, v9)));
                const int mf = kk >> 1, ai = kk & 1;
                ah[mf][ks][ai]     = lo;            // cols c0, c0+1
                ah[mf][ks][ai + 2] = hi;            // cols c0+8, c0+9
            }
        }

        // ---- GEMM + fused per-n-block epilogue ----
        float p0 = 0.f, p1 = 0.f, p2 = 0.f, p3 = 0.f;
        #pragma unroll
        for (int nb = 0; nb < 4; nb++) {
            float acc[2][4][4];
            #pragma unroll
            for (int mf = 0; mf < 2; mf++)
                #pragma unroll
                for (int nf = 0; nf < 4; nf++)
                    #pragma unroll
                    for (int q = 0; q < 4; q++) acc[mf][nf][q] = 0.0f;

            #pragma unroll
            for (int ks = 0; ks < 8; ks++) {
                uint32_t bh[4][2];
                uint32_t bA = bAddr0 + (uint32_t)(nb * 32 * PITCH_B + ks * 32);
                ldsm4(bh[0][0], bh[0][1], bh[1][0], bh[1][1], bA);
                ldsm4(bh[2][0], bh[2][1], bh[3][0], bh[3][1],
                      bA + (uint32_t)(16 * PITCH_B));
                #pragma unroll
                for (int mf = 0; mf < 2; mf++)
                    #pragma unroll
                    for (int nf = 0; nf < 4; nf++)
                        mma_f16(acc[mf][nf], ah[mf][ks], bh[nf]);
            }
            #pragma unroll
            for (int mf = 0; mf < 2; mf++)
                #pragma unroll
                for (int nf = 0; nf < 4; nf++) {
                    const int k = nb * 32 + nf * 8 + cq;
                    float2 c0 = bw[k], c1 = bw[k + 1];
                    float e0 = tanh_a32(acc[mf][nf][0] + c0.x) * c0.y
                             + tanh_a32(acc[mf][nf][1] + c1.x) * c1.y;
                    float e1 = tanh_a32(acc[mf][nf][2] + c0.x) * c0.y
                             + tanh_a32(acc[mf][nf][3] + c1.x) * c1.y;
                    if (mf == 0) { p0 += e0; p1 += e1; }
                    else         { p2 += e0; p3 += e1; }
                }
        }

        // ---- warp reduction: rows r, r+8, r+16, r+24 ----
        p0 += __shfl_xor_sync(0xffffffffu, p0, 1);
        p0 += __shfl_xor_sync(0xffffffffu, p0, 2);
        p1 += __shfl_xor_sync(0xffffffffu, p1, 1);
        p1 += __shfl_xor_sync(0xffffffffu, p1, 2);
        p2 += __shfl_xor_sync(0xffffffffu, p2, 1);
        p2 += __shfl_xor_sync(0xffffffffu, p2, 2);
        p3 += __shfl_xor_sync(0xffffffffu, p3, 1);
        p3 += __shfl_xor_sync(0xffffffffu, p3, 2);
        float s = p0 * __shfl_sync(0xffffffffu, y_own, r)
                + p1 * __shfl_sync(0xffffffffu, y_own, r + 8)
                + p2 * __shfl_sync(0xffffffffu, y_own, r + 16)
                + p3 * __shfl_sync(0xffffffffu, y_own, r + 24);
        if (lane & 3) s = 0.0f;
        #pragma unroll
        for (int o = 16; o > 0; o >>= 1)
            s += __shfl_xor_sync(0xffffffffu, s, o);
        if (lane == 0) g_part[cid] = s;
    }

    // ---- finalize tail: last CTA computes Y and sums g_part -> out ----
    unsigned int* is_last = (unsigned int*)(smem + SM_FLAG);
    __threadfence();                      // publish g_part before ticket
    __syncthreads();
    if (tid == 0)
        *is_last = (atomicAdd(&g_done, 1u) == (unsigned)(NCTA - 1)) ? 1u : 0u;
    __syncthreads();
    if (*is_last) {
        float* yall = (float*)(smem + SM_W2);            // W2 area is dead
        for (int j = tid; j < M_PTS; j += 256) {
            float2 q = *(const float2*)(qxs + 2 * j);
            yall[j] = sinf(epi * q.x) * sinf(epi * q.y);
        }
        __syncthreads();
        if (tid < 16) {
            float p = 0.0f;
            #pragma unroll
            for (int k = 0; k < 32; k++) p += yall[tid * 32 + k];
            yall[M_PTS + tid] = p;
        }
        __syncthreads();
        if (tid == 0) {
            float Y = 0.0f;
            #pragma unroll
            for (int k = 0; k < 16; k++) Y += yall[M_PTS + k];
            yall[M_PTS + 16] = b3[0] * Y;
        }
        __syncthreads();
        const float basev = yall[M_PTS + 16];
        for (int i = tid; i < N_PTS; i += 256) {
            float s2 = basev;
            #pragma unroll
            for (int t = 0; t < JTW; t++) s2 += g_part[i * JTW + t];
            out[i] = s2;
        }
        if (tid == 0) g_done = 0;         // reset: deterministic graph replays
    }
}

// ---------------------------------------------------------------------------
extern "C" void kernel_launch(void* const* d_in, const int* in_sizes, int n_in,
                              void* d_out, int out_size) {
    const float* inp = (const float*)d_in[0];   // [2048, 2]
    const float* qx  = (const float*)d_in[1];   // [512, 2]
    const float* ep  = (const float*)d_in[2];   // [1]
    const float* W1  = (const float*)d_in[3];   // [4, 128]
    const float* b1  = (const float*)d_in[4];   // [128]
    const float* W2  = (const float*)d_in[5];   // [128, 128]
    const float* b2  = (const float*)d_in[6];   // [128]
    const float* W3  = (const float*)d_in[7];   // [128, 1]
    const float* b3  = (const float*)d_in[8];   // [1]
    float* out = (float*)d_out;                 // [2048, 1]
    (void)in_sizes; (void)n_in; (void)out_size;

    cudaFuncSetAttribute(modnet_mma_kernel,
                         cudaFuncAttributeMaxDynamicSharedMemorySize, SMEM_TOTAL);

    modnet_mma_kernel<<<NCTA, 256, SMEM_TOTAL>>>(inp, qx, ep, W1, b1,
                                                 W2, b2, W3, b3, out);
}